// round 1
// baseline (speedup 1.0000x reference)
#include <cuda_runtime.h>
#include <math.h>

#define B_SZ     256
#define S_LEN    1024
#define T_LEN    21
#define NFREQ    11
#define NCH      32      /* reduced conv input channels: 21 raw + 11 freq */
#define COUT     64
#define POOL_T   512
#define HID      32
#define NWROWS   46      /* wavelet output rows */
#define ROWP     264     /* padded smem row for conv tile */
#define TS       256     /* conv s-tile */

/* ---------------- device scratch (no runtime allocation allowed) -------- */
__device__ float g_tw[T_LEN * NFREQ * 2];          /* DFT twiddles (cos, -sin) */
__device__ float g_L[NWROWS * T_LEN];              /* wavedec4 linear map */
__device__ float g_weff[NCH * COUT * 4];           /* folded conv weights [ci][c][k(pad4)] */
__device__ float g_feat[B_SZ * NCH * S_LEN];       /* [b][ch][s] */
__device__ float g_pooled[B_SZ * POOL_T * COUT];   /* [b][t][c]  LSTM input */

__constant__ float c_lo[8] = {
    -0.010597401784997278f,  0.032883011666982945f,  0.030841381835986965f,
    -0.18703481171888114f,  -0.02798376941698385f,   0.6308807679295904f,
     0.7148465705525415f,    0.23037781330885523f };
__constant__ float c_hi[8] = {
    -0.23037781330885523f,   0.7148465705525415f,   -0.6308807679295904f,
    -0.02798376941698385f,   0.18703481171888114f,   0.030841381835986965f,
    -0.032883011666982945f, -0.010597401784997278f };

/* ============ K0: twiddles, wavelet linear map L, folded conv weights === */
__global__ void precompute_kernel(const float* __restrict__ conv_w)
{
    int tid = threadIdx.x;

    /* DFT twiddles: e^{-2*pi*i*k*n/21} */
    for (int i = tid; i < T_LEN * NFREQ; i += blockDim.x) {
        int n = i / NFREQ, k = i % NFREQ;
        double ang = 2.0 * (double)(k * n) / 21.0;   /* cos(pi*ang) */
        g_tw[2 * i]     = (float)cospi(ang);
        g_tw[2 * i + 1] = (float)(-sinpi(ang));
    }

    /* L: wavedec4 of identity basis vectors. Thread t handles basis e_t.   */
    if (tid < T_LEN) {
        float a[21];
        #pragma unroll
        for (int i = 0; i < 21; i++) a[i] = (i == tid) ? 1.f : 0.f;
        int n = 21;
        const int rowbase[4] = {32, 22, 14, 7};   /* cD1,cD2,cD3,cD4 rows */
        for (int lev = 0; lev < 4; lev++) {
            int mout = (n + 5) / 2 + 1;           /* (n+13-8)/2+1 */
            float cA[14];
            for (int m = 0; m < mout; m++) {
                float aL = 0.f, aH = 0.f;
                #pragma unroll
                for (int j = 0; j < 8; j++) {
                    int idx = 2 * m + 1 - j;      /* symmetric extension */
                    if (idx < 0)  idx = -idx - 1;
                    if (idx >= n) idx = 2 * n - 1 - idx;
                    aL += c_lo[j] * a[idx];
                    aH += c_hi[j] * a[idx];
                }
                cA[m] = aL;
                g_L[(rowbase[lev] + m) * T_LEN + tid] = aH;
            }
            for (int m = 0; m < mout; m++) a[m] = cA[m];
            n = mout;
        }
        for (int m = 0; m < n; m++)               /* cA4 -> rows 0..6 */
            g_L[m * T_LEN + tid] = a[m];
    }
    __syncthreads();

    /* w_eff[c][ci][k]: raw/freq channels pass through; wavelet channels fold */
    for (int idx = tid; idx < COUT * NCH; idx += blockDim.x) {
        int c  = idx / NCH;
        int ci = idx % NCH;
        for (int k = 0; k < 3; k++) {
            float val = conv_w[(c * 78 + ci) * 3 + k];
            if (ci < T_LEN) {
                for (int j = 0; j < NWROWS; j++)
                    val += conv_w[(c * 78 + 32 + j) * 3 + k] * g_L[j * T_LEN + ci];
            }
            g_weff[(ci * COUT + c) * 4 + k] = val;
        }
        g_weff[(ci * COUT + c) * 4 + 3] = 0.f;
    }
}

/* ============ K1: feat[b][ch][s] = [x(21), |rfft|(11)] ==================== */
__global__ void __launch_bounds__(128) feat_kernel(const float* __restrict__ x)
{
    __shared__ float sx[128 * T_LEN];
    __shared__ float stw[T_LEN * NFREQ * 2];

    int b  = blockIdx.x >> 3;
    int s0 = (blockIdx.x & 7) << 7;
    int tid = threadIdx.x;

    for (int i = tid; i < 128 * T_LEN; i += 128)
        sx[i] = x[(size_t)(b * S_LEN + s0) * T_LEN + i];
    for (int i = tid; i < T_LEN * NFREQ * 2; i += 128)
        stw[i] = g_tw[i];
    __syncthreads();

    float xr[T_LEN];
    #pragma unroll
    for (int i = 0; i < T_LEN; i++) xr[i] = sx[tid * T_LEN + i];

    int s = s0 + tid;
    float* fb = g_feat + (size_t)b * NCH * S_LEN + s;
    #pragma unroll
    for (int i = 0; i < T_LEN; i++) fb[i * S_LEN] = xr[i];

    for (int k = 0; k < NFREQ; k++) {
        float re = 0.f, im = 0.f;
        #pragma unroll
        for (int n = 0; n < T_LEN; n++) {
            float cw = stw[(n * NFREQ + k) * 2];
            float sw = stw[(n * NFREQ + k) * 2 + 1];
            re = fmaf(xr[n], cw, re);
            im = fmaf(xr[n], sw, im);
        }
        fb[(T_LEN + k) * S_LEN] = sqrtf(re * re + im * im);
    }
}

/* ============ K2: conv3(32->64) + ReLU + maxpool2 -> pooled[b][t][c] ===== */
__global__ void __launch_bounds__(256) conv_pool_kernel(const float* __restrict__ conv_b)
{
    extern __shared__ float sm[];
    float* sin_ = sm;                 /* 32 x ROWP input tile */
    float* sw   = sm + NCH * ROWP;    /* 8192 folded weights  */

    int b  = blockIdx.x >> 2;
    int s0 = (blockIdx.x & 3) * TS;
    int tid = threadIdx.x;

    for (int i = tid; i < NCH * COUT * 4; i += 256) sw[i] = g_weff[i];

    const float* fb = g_feat + (size_t)b * NCH * S_LEN;
    for (int i = tid; i < NCH * (TS + 2); i += 256) {
        int ci = i / (TS + 2), col = i % (TS + 2);
        int s = s0 + col - 1;
        sin_[ci * ROWP + col] = (s >= 0 && s < S_LEN) ? fb[ci * S_LEN + s] : 0.f;
    }
    __syncthreads();

    int c  = tid & 63;
    int sg = tid >> 6;
    float bias = conv_b[c];
    float* pout = g_pooled + (size_t)b * POOL_T * COUT + c;

    for (int ch = 0; ch < 8; ch++) {
        int cs = sg * 64 + ch * 8;                /* chunk of 8 outputs */
        float acc[8];
        #pragma unroll
        for (int i = 0; i < 8; i++) acc[i] = bias;

        for (int ci = 0; ci < NCH; ci++) {
            const float4* row = (const float4*)(sin_ + ci * ROWP + cs);
            float4 v0 = row[0], v1 = row[1], v2 = row[2];
            float4 w  = *(const float4*)(sw + (ci * COUT + c) * 4);
            float v[12] = { v0.x, v0.y, v0.z, v0.w,
                            v1.x, v1.y, v1.z, v1.w,
                            v2.x, v2.y, v2.z, v2.w };
            #pragma unroll
            for (int i = 0; i < 8; i++)
                acc[i] = fmaf(w.x, v[i], fmaf(w.y, v[i + 1], fmaf(w.z, v[i + 2], acc[i])));
        }

        int t0 = (s0 + cs) >> 1;
        #pragma unroll
        for (int i = 0; i < 4; i++) {
            float a0 = fmaxf(acc[2 * i],     0.f);
            float a1 = fmaxf(acc[2 * i + 1], 0.f);
            pout[(t0 + i) * COUT] = fmaxf(a0, a1);
        }
    }
}

/* ============ K3: LSTM (1 CTA per batch, 4 warps = gates i,f,g,o) + FC === */
__device__ __forceinline__ float sigmoid_f(float z) {
    return 1.f / (1.f + __expf(-z));
}
__device__ __forceinline__ float tanh_f(float z) {
    float e = __expf(-2.f * fabsf(z));
    float t = (1.f - e) / (1.f + e);
    return copysignf(t, z);
}

__global__ void __launch_bounds__(128) lstm_kernel(
    const float* __restrict__ w_ih, const float* __restrict__ w_hh,
    const float* __restrict__ b_ih, const float* __restrict__ b_hh,
    const float* __restrict__ fc_w, const float* __restrict__ fc_b,
    float* __restrict__ out)
{
    __shared__ __align__(16) float s_h[HID];
    __shared__ __align__(16) float s_a[4][HID];
    __shared__ __align__(16) float s_x[2][COUT];

    int b    = blockIdx.x;
    int tid  = threadIdx.x;
    int w    = tid >> 5;
    int lane = tid & 31;
    int g    = w * 32 + lane;

    float wih[64], whh[32];
    #pragma unroll
    for (int q = 0; q < 16; q++) {
        float4 v = ((const float4*)(w_ih + g * 64))[q];
        wih[4*q] = v.x; wih[4*q+1] = v.y; wih[4*q+2] = v.z; wih[4*q+3] = v.w;
    }
    #pragma unroll
    for (int q = 0; q < 8; q++) {
        float4 v = ((const float4*)(w_hh + g * 32))[q];
        whh[4*q] = v.x; whh[4*q+1] = v.y; whh[4*q+2] = v.z; whh[4*q+3] = v.w;
    }
    float bias = b_ih[g] + b_hh[g];
    float cst = 0.f;

    const float* xp = g_pooled + (size_t)b * POOL_T * COUT;
    if (tid < HID)  s_h[tid] = 0.f;
    if (tid < COUT) s_x[0][tid] = xp[tid];
    __syncthreads();

    for (int t = 0; t < POOL_T; t++) {
        /* prefetch next x_t early (latency hidden behind matvec) */
        float rx = 0.f;
        if (tid >= 64 && t + 1 < POOL_T) rx = xp[(t + 1) * COUT + (tid - 64)];

        /* gate = b + w_ih . x_t + w_hh . h   (4 independent FMA chains)    */
        float a0 = 0.f, a1 = 0.f, a2 = 0.f, a3 = 0.f;
        const float4* x4 = (const float4*)s_x[t & 1];
        #pragma unroll
        for (int q = 0; q < 16; q++) {
            float4 v = x4[q];
            a0 = fmaf(wih[4*q],   v.x, a0);
            a1 = fmaf(wih[4*q+1], v.y, a1);
            a2 = fmaf(wih[4*q+2], v.z, a2);
            a3 = fmaf(wih[4*q+3], v.w, a3);
        }
        const float4* h4 = (const float4*)s_h;
        #pragma unroll
        for (int q = 0; q < 8; q++) {
            float4 v = h4[q];
            a0 = fmaf(whh[4*q],   v.x, a0);
            a1 = fmaf(whh[4*q+1], v.y, a1);
            a2 = fmaf(whh[4*q+2], v.z, a2);
            a3 = fmaf(whh[4*q+3], v.w, a3);
        }
        float z = bias + (a0 + a1) + (a2 + a3);
        float act = (w == 2) ? tanh_f(z) : sigmoid_f(z);
        s_a[w][lane] = act;
        __syncthreads();

        if (w == 0) {                         /* i-warp owns c and h update */
            float ai = act;
            float af = s_a[1][lane];
            float ag = s_a[2][lane];
            float ao = s_a[3][lane];
            cst = fmaf(af, cst, ai * ag);
            s_h[lane] = ao * tanh_f(cst);
        }
        if (tid >= 64 && t + 1 < POOL_T) s_x[(t + 1) & 1][tid - 64] = rx;
        __syncthreads();
    }

    if (w == 0) {
        float v = fc_w[lane] * s_h[lane];
        #pragma unroll
        for (int off = 16; off; off >>= 1)
            v += __shfl_down_sync(0xffffffffu, v, off);
        if (lane == 0) out[b] = v + fc_b[0];
    }
}

/* ======================================================================== */
extern "C" void kernel_launch(void* const* d_in, const int* in_sizes, int n_in,
                              void* d_out, int out_size)
{
    const float* x      = (const float*)d_in[0];
    const float* conv_w = (const float*)d_in[1];
    const float* conv_b = (const float*)d_in[2];
    const float* w_ih   = (const float*)d_in[3];
    const float* w_hh   = (const float*)d_in[4];
    const float* b_ih   = (const float*)d_in[5];
    const float* b_hh   = (const float*)d_in[6];
    const float* fc_w   = (const float*)d_in[7];
    const float* fc_b   = (const float*)d_in[8];
    float* out = (float*)d_out;

    precompute_kernel<<<1, 256>>>(conv_w);
    feat_kernel<<<B_SZ * 8, 128>>>(x);

    size_t smem = (size_t)(NCH * ROWP + NCH * COUT * 4) * sizeof(float);
    cudaFuncSetAttribute(conv_pool_kernel,
                         cudaFuncAttributeMaxDynamicSharedMemorySize, (int)smem);
    conv_pool_kernel<<<B_SZ * 4, 256, smem>>>(conv_b);

    lstm_kernel<<<B_SZ, 128>>>(w_ih, w_hh, b_ih, b_hh, fc_w, fc_b, out);
}